// round 10
// baseline (speedup 1.0000x reference)
#include <cuda_runtime.h>

// DCN cross, split into reduction + streaming:
//   K1: a[row] via collapsed recurrence (d_l = x.W_l, c_l/v from block preamble)
//   K2: out[row,:] = a[row] * x[row,:] + v[:]   (pure coalesced axpy, x L2-hot)

constexpr int D = 256;
constexpr int L = 4;

__device__ float g_a[8192];
__device__ float g_v[D];

// ---------------- K1: per-row scalar a ----------------
__global__ __launch_bounds__(256)
void k1_reduce(const float* __restrict__ x,
               const float* __restrict__ W,
               const float* __restrict__ b_lin,
               const float* __restrict__ bias,
               int B)
{
    __shared__ float W_sm[L * D];
    __shared__ float c_part[8 * L];
    __shared__ float c_sm[L];

    const int tid  = threadIdx.x;
    const int warp = tid >> 5;
    const int lane = tid & 31;
    const int j    = lane & 15;
    const int sub  = lane >> 4;
    const int row  = blockIdx.x * 16 + warp * 2 + sub;

    // x loads first — hidden behind the preamble
    float4 xq[4];
    if (row < B) {
        const float4* xr = reinterpret_cast<const float4*>(x + (size_t)row * D);
        #pragma unroll
        for (int k = 0; k < 4; ++k) xq[k] = xr[k * 16 + j];
    }

    // preamble: W->smem, v vector, c scalars (once per block)
    {
        float v = 0.0f;
        float cp[L];
        #pragma unroll
        for (int l = 0; l < L; ++l) {
            const float w = W[l * D + tid];
            W_sm[l * D + tid] = w;
            cp[l] = v * w;                          // c_l uses v BEFORE update
            v += b_lin[l] + bias[l * D + tid];
        }
        if (blockIdx.x == 0) g_v[tid] = v;          // publish v once
        #pragma unroll
        for (int o = 16; o > 0; o >>= 1) {
            #pragma unroll
            for (int l = 0; l < L; ++l)
                cp[l] += __shfl_xor_sync(0xffffffffu, cp[l], o);
        }
        if (lane == 0) {
            #pragma unroll
            for (int l = 0; l < L; ++l) c_part[warp * L + l] = cp[l];
        }
    }
    __syncthreads();
    if (tid < L) {
        float s = 0.0f;
        #pragma unroll
        for (int w8 = 0; w8 < 8; ++w8) s += c_part[w8 * L + tid];
        c_sm[tid] = s;
    }
    __syncthreads();

    if (row >= B) return;

    // dots d_l = x . W_l (smem broadcast)
    const float4* Wv = reinterpret_cast<const float4*>(W_sm);
    float d[L];
    #pragma unroll
    for (int l = 0; l < L; ++l) {
        float a0 = 0.f, a1 = 0.f, a2 = 0.f, a3 = 0.f;
        #pragma unroll
        for (int k = 0; k < 4; ++k) {
            const float4 w = Wv[l * 64 + k * 16 + j];
            a0 = fmaf(xq[k].x, w.x, a0);
            a1 = fmaf(xq[k].y, w.y, a1);
            a2 = fmaf(xq[k].z, w.z, a2);
            a3 = fmaf(xq[k].w, w.w, a3);
        }
        d[l] = (a0 + a1) + (a2 + a3);
    }

    // width-16 ladder, both rows at once
    #pragma unroll
    for (int o = 8; o > 0; o >>= 1) {
        #pragma unroll
        for (int l = 0; l < L; ++l)
            d[l] += __shfl_xor_sync(0xffffffffu, d[l], o);
    }

    // scalar recurrence a += a*d_l + c_l
    float a = 1.0f;
    #pragma unroll
    for (int l = 0; l < L; ++l)
        a = fmaf(a, d[l], a + c_sm[l]);

    if (j == 0) g_a[row] = a;
}

// ---------------- K2: streaming axpy ----------------
// thread handles 4 float4s; g = blk*1024 + k*256 + tid; row = g >> 6.
__global__ __launch_bounds__(256)
void k2_axpy(const float* __restrict__ x,
             float* __restrict__ out,
             int nq)   // total float4 count = B*64
{
    const float4* x4 = reinterpret_cast<const float4*>(x);
    float4*       o4 = reinterpret_cast<float4*>(out);
    const float4* v4 = reinterpret_cast<const float4*>(g_v);

    const int base = blockIdx.x * 1024 + threadIdx.x;
    #pragma unroll
    for (int k = 0; k < 4; ++k) {
        const int g = base + k * 256;
        if (g < nq) {
            const float a  = g_a[g >> 6];        // broadcast within warp
            const float4 v = v4[g & 63];         // L1-hot
            const float4 xv = x4[g];             // L2-hot after K1
            float4 r;
            r.x = fmaf(a, xv.x, v.x);
            r.y = fmaf(a, xv.y, v.y);
            r.z = fmaf(a, xv.z, v.z);
            r.w = fmaf(a, xv.w, v.w);
            o4[g] = r;
        }
    }
}

extern "C" void kernel_launch(void* const* d_in, const int* in_sizes, int n_in,
                              void* d_out, int out_size)
{
    const float* x     = (const float*)d_in[0];
    const float* W     = (const float*)d_in[1];
    const float* b_lin = (const float*)d_in[2];
    const float* bias  = (const float*)d_in[3];
    float* out         = (float*)d_out;

    const int B  = in_sizes[0] / D;        // 8192
    const int nq = B * (D / 4);            // 524288 float4s

    k1_reduce<<<(B + 15) / 16, 256>>>(x, W, b_lin, bias, B);
    k2_axpy<<<(nq + 1023) / 1024, 256>>>(x, out, nq);
}

// round 11
// speedup vs baseline: 1.0652x; 1.0652x over previous
#include <cuda_runtime.h>

// DCN cross, B=8192, D=256, L=4 — collapsed algebra, max warp concurrency:
//   out = a_L*x0 + v_L,  a_{l+1} = a_l*(1+d_l) + c_l,  d_l = x0.W_l
//   v_L / c_l row-independent: block preamble into smem.
// Mapping: 32 lanes/row, 1 row/warp -> 8192 warps (~55/SM) for latency hiding.
// Per warp: 2 LDG.128 (x), 2 STG.128 (out), smem W/v reads, 20 SHFL.

constexpr int D = 256;
constexpr int L = 4;
constexpr int ROWS_PER_BLOCK = 8;   // 8 warps/block, 1 row/warp

__global__ __launch_bounds__(256)
void cross_kernel(const float* __restrict__ x,
                  const float* __restrict__ W,
                  const float* __restrict__ b_lin,
                  const float* __restrict__ bias,
                  float* __restrict__ out,
                  int B)
{
    __shared__ float W_sm[L * D];     // 4 KB
    __shared__ float v_sm[D];         // 1 KB
    __shared__ float c_part[8 * L];
    __shared__ float c_sm[L];

    const int tid  = threadIdx.x;
    const int warp = tid >> 5;
    const int lane = tid & 31;
    const int row  = blockIdx.x * ROWS_PER_BLOCK + warp;

    // ---- x loads first (2 independent LDG.128), hidden behind preamble ----
    const float4* xr = reinterpret_cast<const float4*>(x + (size_t)row * D);
    float4 xq[2];
    xq[0] = xr[lane];
    xq[1] = xr[lane + 32];

    // ---- preamble (once per block): W->smem, v_L, c_l ----
    {
        float v = 0.0f;
        float cp[L];
        #pragma unroll
        for (int l = 0; l < L; ++l) {
            const float w = W[l * D + tid];
            W_sm[l * D + tid] = w;
            cp[l] = v * w;                        // c_l uses v BEFORE update
            v += b_lin[l] + bias[l * D + tid];
        }
        v_sm[tid] = v;
        #pragma unroll
        for (int o = 16; o > 0; o >>= 1) {
            #pragma unroll
            for (int l = 0; l < L; ++l)
                cp[l] += __shfl_xor_sync(0xffffffffu, cp[l], o);
        }
        if (lane == 0) {
            #pragma unroll
            for (int l = 0; l < L; ++l) c_part[warp * L + l] = cp[l];
        }
    }
    __syncthreads();
    if (tid < L) {
        float s = 0.0f;
        #pragma unroll
        for (int w8 = 0; w8 < 8; ++w8) s += c_part[w8 * L + tid];
        c_sm[tid] = s;
    }
    __syncthreads();

    // ---- dots: d_l = x0 . W_l (W broadcast from smem) ----
    const float4* Wv = reinterpret_cast<const float4*>(W_sm);
    float d[L];
    #pragma unroll
    for (int l = 0; l < L; ++l) {
        const float4 w0 = Wv[l * 64 + lane];
        const float4 w1 = Wv[l * 64 + lane + 32];
        float a0 = xq[0].x * w0.x;
        float a1 = xq[0].y * w0.y;
        float a2 = xq[0].z * w0.z;
        float a3 = xq[0].w * w0.w;
        a0 = fmaf(xq[1].x, w1.x, a0);
        a1 = fmaf(xq[1].y, w1.y, a1);
        a2 = fmaf(xq[1].z, w1.z, a2);
        a3 = fmaf(xq[1].w, w1.w, a3);
        d[l] = (a0 + a1) + (a2 + a3);
    }

    // ---- 5-step butterfly: 4 independent ladders pipeline each other ----
    #pragma unroll
    for (int o = 16; o > 0; o >>= 1) {
        #pragma unroll
        for (int l = 0; l < L; ++l)
            d[l] += __shfl_xor_sync(0xffffffffu, d[l], o);
    }

    // ---- scalar recurrence: a += a*d_l + c_l ----
    float a = 1.0f;
    #pragma unroll
    for (int l = 0; l < L; ++l)
        a = fmaf(a, d[l], a + c_sm[l]);

    // ---- epilogue: out = a*x0 + v_L ----
    const float4* vr = reinterpret_cast<const float4*>(v_sm);
    const float4 v0 = vr[lane];
    const float4 v1 = vr[lane + 32];
    float4* orow = reinterpret_cast<float4*>(out + (size_t)row * D);
    float4 o4;
    o4.x = fmaf(a, xq[0].x, v0.x);
    o4.y = fmaf(a, xq[0].y, v0.y);
    o4.z = fmaf(a, xq[0].z, v0.z);
    o4.w = fmaf(a, xq[0].w, v0.w);
    orow[lane] = o4;
    o4.x = fmaf(a, xq[1].x, v1.x);
    o4.y = fmaf(a, xq[1].y, v1.y);
    o4.z = fmaf(a, xq[1].z, v1.z);
    o4.w = fmaf(a, xq[1].w, v1.w);
    orow[lane + 32] = o4;
}

extern "C" void kernel_launch(void* const* d_in, const int* in_sizes, int n_in,
                              void* d_out, int out_size)
{
    const float* x     = (const float*)d_in[0];
    const float* W     = (const float*)d_in[1];
    const float* b_lin = (const float*)d_in[2];
    const float* bias  = (const float*)d_in[3];
    float* out         = (float*)d_out;

    const int B = in_sizes[0] / D;                                // 8192
    const int blocks = (B + ROWS_PER_BLOCK - 1) / ROWS_PER_BLOCK; // 1024

    cross_kernel<<<blocks, 256>>>(x, W, b_lin, bias, out, B);
}

// round 12
// speedup vs baseline: 1.2294x; 1.1541x over previous
#include <cuda_runtime.h>

// DCN cross, B=8192, D=256, L=4 — collapsed algebra (R7 structure) + cache tuning:
//   out = a_L*x0 + v_L,  a_{l+1} = a_l*(1+d_l) + c_l,  d_l = x0.W_l
//   v_L/c_l row-independent: block preamble into smem.
// 16 lanes/row, 2 rows/warp, 8 warps/block, grid 512.
// x loads / out stores use .cg (L2-only) — single-use data, keep L1 clean.

constexpr int D = 256;
constexpr int L = 4;
constexpr int ROWS_PER_BLOCK = 16;

__device__ __forceinline__ float4 ldg_cg(const float4* p) {
    float4 v;
    asm volatile("ld.global.cg.v4.f32 {%0,%1,%2,%3}, [%4];"
                 : "=f"(v.x), "=f"(v.y), "=f"(v.z), "=f"(v.w) : "l"(p));
    return v;
}
__device__ __forceinline__ void stg_cg(float4* p, float4 v) {
    asm volatile("st.global.cg.v4.f32 [%0], {%1,%2,%3,%4};"
                 :: "l"(p), "f"(v.x), "f"(v.y), "f"(v.z), "f"(v.w) : "memory");
}

__global__ __launch_bounds__(256)
void cross_kernel(const float* __restrict__ x,
                  const float* __restrict__ W,
                  const float* __restrict__ b_lin,
                  const float* __restrict__ bias,
                  float* __restrict__ out)
{
    __shared__ float W_sm[L * D];     // 4 KB
    __shared__ float v_sm[D];         // 1 KB
    __shared__ float c_part[8 * L];
    __shared__ float c_sm[L];

    const int tid  = threadIdx.x;
    const int warp = tid >> 5;
    const int lane = tid & 31;
    const int j    = lane & 15;       // slot within 16-lane row group
    const int row  = blockIdx.x * ROWS_PER_BLOCK + warp * 2 + (lane >> 4);

    // ---- x loads first (4 independent LDG.128.cg), hidden behind preamble ----
    const float4* xr = reinterpret_cast<const float4*>(x + (size_t)row * D);
    float4 xq[4];
    #pragma unroll
    for (int k = 0; k < 4; ++k) xq[k] = ldg_cg(xr + k * 16 + j);

    // ---- preamble (once per block): W->smem, v_L, c_l ----
    {
        float v = 0.0f;
        float cp[L];
        #pragma unroll
        for (int l = 0; l < L; ++l) {
            const float w = W[l * D + tid];
            W_sm[l * D + tid] = w;
            cp[l] = v * w;                        // c_l uses v BEFORE update
            v += b_lin[l] + bias[l * D + tid];
        }
        v_sm[tid] = v;
        #pragma unroll
        for (int o = 16; o > 0; o >>= 1) {
            #pragma unroll
            for (int l = 0; l < L; ++l)
                cp[l] += __shfl_xor_sync(0xffffffffu, cp[l], o);
        }
        if (lane == 0) {
            #pragma unroll
            for (int l = 0; l < L; ++l) c_part[warp * L + l] = cp[l];
        }
    }
    __syncthreads();
    if (tid < L) {
        float s = 0.0f;
        #pragma unroll
        for (int w8 = 0; w8 < 8; ++w8) s += c_part[w8 * L + tid];
        c_sm[tid] = s;
    }
    __syncthreads();

    // ---- dots: d_l = x0 . W_l (W broadcast from smem) ----
    const float4* Wv = reinterpret_cast<const float4*>(W_sm);
    float d[L];
    #pragma unroll
    for (int l = 0; l < L; ++l) {
        float a0 = 0.f, a1 = 0.f, a2 = 0.f, a3 = 0.f;
        #pragma unroll
        for (int k = 0; k < 4; ++k) {
            const float4 w = Wv[l * 64 + k * 16 + j];
            a0 = fmaf(xq[k].x, w.x, a0);
            a1 = fmaf(xq[k].y, w.y, a1);
            a2 = fmaf(xq[k].z, w.z, a2);
            a3 = fmaf(xq[k].w, w.w, a3);
        }
        d[l] = (a0 + a1) + (a2 + a3);
    }

    // ---- 4-step width-16 ladder: one SHFL reduces both rows of the warp ----
    #pragma unroll
    for (int o = 8; o > 0; o >>= 1) {
        #pragma unroll
        for (int l = 0; l < L; ++l)
            d[l] += __shfl_xor_sync(0xffffffffu, d[l], o);
    }

    // ---- scalar recurrence: a += a*d_l + c_l ----
    float a = 1.0f;
    #pragma unroll
    for (int l = 0; l < L; ++l)
        a = fmaf(a, d[l], a + c_sm[l]);

    // ---- epilogue: out = a*x0 + v_L  (stores bypass L1) ----
    const float4* vr = reinterpret_cast<const float4*>(v_sm);
    float4* orow = reinterpret_cast<float4*>(out + (size_t)row * D);
    #pragma unroll
    for (int k = 0; k < 4; ++k) {
        const float4 v = vr[k * 16 + j];
        float4 o4;
        o4.x = fmaf(a, xq[k].x, v.x);
        o4.y = fmaf(a, xq[k].y, v.y);
        o4.z = fmaf(a, xq[k].z, v.z);
        o4.w = fmaf(a, xq[k].w, v.w);
        stg_cg(orow + k * 16 + j, o4);
    }
}

extern "C" void kernel_launch(void* const* d_in, const int* in_sizes, int n_in,
                              void* d_out, int out_size)
{
    const float* x     = (const float*)d_in[0];
    const float* W     = (const float*)d_in[1];
    const float* b_lin = (const float*)d_in[2];
    const float* bias  = (const float*)d_in[3];
    float* out         = (float*)d_out;

    const int B = in_sizes[0] / D;                                // 8192
    const int blocks = (B + ROWS_PER_BLOCK - 1) / ROWS_PER_BLOCK; // 512

    cross_kernel<<<blocks, 256>>>(x, W, b_lin, bias, out);
}